// round 2
// baseline (speedup 1.0000x reference)
#include <cuda_runtime.h>
#include <math.h>

#define W   512
#define B   32
#define C   3
#define LIM 0.03125f              // PIX_W * EPS = (2/512)*8
#define DEF_OFF_F (1.0f + 2.0f/511.0f)   // (2 + 4/511)/2

// ---------------- scratch (static device arrays; no runtime allocs) --------
__device__ float d_gw[5];                         // 1D gaussian weights
__device__ float d_blur[(size_t)B * 2 * W * W];   // blurred prim grid (64MB)
__device__ float d_px[(size_t)B * W * W];         // sample x coord in pixels
__device__ float d_py[(size_t)B * W * W];         // sample y coord in pixels

// ---------------- init gaussian weights (double, matches numpy) ------------
__global__ void k_initw() {
    double sigma = 5.0 * 0.15 + 0.35;             // 1.1
    double p[5], s = 0.0;
    #pragma unroll
    for (int i = 0; i < 5; i++) {
        double d = (double)(i - 2) / sigma;
        p[i] = exp(-0.5 * d * d);
        s += p[i];
    }
    #pragma unroll
    for (int i = 0; i < 5; i++) d_gw[i] = (float)(p[i] / s);
}

__device__ __forceinline__ int refl(int i) {
    return i < 0 ? -i : (i >= W ? 2 * W - 2 - i : i);
}

// ---------------- separable 5x5 blur, reflect padding ----------------------
#define TX 64
#define TY 16
__global__ void k_blur(const float* __restrict__ pg) {
    __shared__ float sin_[TY + 4][TX + 4];
    __shared__ float svb[TY][TX + 4];
    int img = blockIdx.z;                         // b*2 + ch
    int bx = blockIdx.x * TX, by = blockIdx.y * TY;
    const float* src = pg + (size_t)img * W * W;
    float w0 = d_gw[0], w1 = d_gw[1], w2 = d_gw[2];
    int tid = threadIdx.x;                        // 256 threads

    for (int i = tid; i < (TY + 4) * (TX + 4); i += 256) {
        int r = i / (TX + 4), c = i % (TX + 4);
        sin_[r][c] = src[(size_t)refl(by + r - 2) * W + refl(bx + c - 2)];
    }
    __syncthreads();
    for (int i = tid; i < TY * (TX + 4); i += 256) {
        int r = i / (TX + 4), c = i % (TX + 4);
        svb[r][c] = w0 * (sin_[r][c] + sin_[r + 4][c])
                  + w1 * (sin_[r + 1][c] + sin_[r + 3][c])
                  + w2 * sin_[r + 2][c];
    }
    __syncthreads();
    float* dst = d_blur + (size_t)img * W * W;
    for (int i = tid; i < TY * TX; i += 256) {
        int r = i / TX, c = i % TX;
        float v = w0 * (svb[r][c] + svb[r][c + 4])
                + w1 * (svb[r][c + 1] + svb[r][c + 3])
                + w2 * svb[r][c + 2];
        dst[(size_t)(by + r) * W + (bx + c)] = v;
    }
}

// ---------------- x-channel: diff -> relu -> inclusive row scan ------------
__global__ void k_rowscan() {
    int row = blockIdx.x;                 // b*W + y
    int x = threadIdx.x;                  // 512 threads
    const float* g = d_blur + ((size_t)((row >> 9) * 2) * W + (row & 511)) * W;

    __shared__ float ss[W];
    __shared__ float wsum[16];

    float iden = (2.0f * x - (float)(W - 1)) * (1.0f / (W - 1));
    float sv = g[x] + iden + DEF_OFF_F;
    ss[x] = sv;
    __syncthreads();
    float a = (x == 0) ? fmaxf(sv, 0.f) : fmaxf(sv - ss[x - 1], 0.f);

    int lane = x & 31, warp = x >> 5;
    float v = a;
    #pragma unroll
    for (int o = 1; o < 32; o <<= 1) {
        float n = __shfl_up_sync(0xffffffffu, v, o);
        if (lane >= o) v += n;
    }
    if (lane == 31) wsum[warp] = v;
    __syncthreads();
    if (warp == 0) {
        float wv = (lane < 16) ? wsum[lane] : 0.f;
        #pragma unroll
        for (int o = 1; o < 16; o <<= 1) {
            float n = __shfl_up_sync(0xffffffffu, wv, o);
            if (lane >= o) wv += n;
        }
        if (lane < 16) wsum[lane] = wv;
    }
    __syncthreads();
    float sx2 = v + (warp ? wsum[warp - 1] : 0.f);

    float pgv = sx2 - DEF_OFF_F - iden;
    pgv = fminf(fmaxf(pgv, -LIM), LIM);
    float gx = fminf(fmaxf(pgv + iden, -1.f), 1.f);
    d_px[(size_t)row * W + x] = (gx + 1.f) * 0.5f * (float)(W - 1);
}

// ---------------- y-channel: serial column scan ----------------------------
__global__ void k_colscan() {
    int idx = blockIdx.x * blockDim.x + threadIdx.x;   // b*W + x
    if (idx >= B * W) return;
    int b = idx >> 9, x = idx & 511;
    const float* g = d_blur + (size_t)(b * 2 + 1) * W * W + x;
    float* py = d_py + (size_t)b * W * W + x;

    // y = 0
    float iden0 = -1.0f;
    float sv = g[0] + iden0 + DEF_OFF_F;
    float prev = sv;
    float acc = fmaxf(sv, 0.f);
    {
        float pgv = acc - DEF_OFF_F - iden0;
        pgv = fminf(fmaxf(pgv, -LIM), LIM);
        float gy = fminf(fmaxf(pgv + iden0, -1.f), 1.f);
        py[0] = (gy + 1.f) * 0.5f * (float)(W - 1);
    }
    #pragma unroll 8
    for (int y = 1; y < W; y++) {
        float iden = (2.0f * y - (float)(W - 1)) * (1.0f / (W - 1));
        float s2 = g[(size_t)y * W] + iden + DEF_OFF_F;
        float a = fmaxf(s2 - prev, 0.f);
        prev = s2;
        acc += a;
        float pgv = acc - DEF_OFF_F - iden;
        pgv = fminf(fmaxf(pgv, -LIM), LIM);
        float gy = fminf(fmaxf(pgv + iden, -1.f), 1.f);
        py[(size_t)y * W] = (gy + 1.f) * 0.5f * (float)(W - 1);
    }
}

// ---------------- bilinear grid sample --------------------------------------
__global__ void k_sample(const float* __restrict__ img, float* __restrict__ out) {
    int idx = blockIdx.x * blockDim.x + threadIdx.x;   // b*W*W + y*W + x
    if (idx >= B * W * W) return;
    int x = idx & 511, y = (idx >> 9) & 511, b = idx >> 18;

    float fx = d_px[idx], fy = d_py[idx];
    float x0f = floorf(fx), y0f = floorf(fy);
    int x0 = (int)x0f, y0 = (int)y0f;
    int x1 = x0 + 1, y1 = y0 + 1;
    float wx1 = fx - x0f, wx0 = 1.f - wx1;
    float wy1 = fy - y0f, wy0 = 1.f - wy1;

    bool vx0 = (x0 >= 0) & (x0 < W);
    bool vx1 = (x1 >= 0) & (x1 < W);
    bool vy0 = (y0 >= 0) & (y0 < W);
    bool vy1 = (y1 >= 0) & (y1 < W);

    int x0c = min(max(x0, 0), W - 1), x1c = min(max(x1, 0), W - 1);
    int y0c = min(max(y0, 0), W - 1), y1c = min(max(y1, 0), W - 1);

    float w00 = wx0 * wy0 * (float)(vx0 && vy0);
    float w10 = wx1 * wy0 * (float)(vx1 && vy0);
    float w01 = wx0 * wy1 * (float)(vx0 && vy1);
    float w11 = wx1 * wy1 * (float)(vx1 && vy1);

    const float* ib = img + (size_t)b * C * W * W;
    size_t o00 = (size_t)y0c * W + x0c, o10 = (size_t)y0c * W + x1c;
    size_t o01 = (size_t)y1c * W + x0c, o11 = (size_t)y1c * W + x1c;
    #pragma unroll
    for (int c = 0; c < C; c++) {
        const float* ic = ib + (size_t)c * W * W;
        float v = w00 * __ldg(ic + o00) + w10 * __ldg(ic + o10)
                + w01 * __ldg(ic + o01) + w11 * __ldg(ic + o11);
        out[((size_t)(b * C + c) * W + y) * W + x] = v;
    }
}

// ---------------- launch -----------------------------------------------------
extern "C" void kernel_launch(void* const* d_in, const int* in_sizes, int n_in,
                              void* d_out, int out_size) {
    const float* image = (const float*)d_in[0];
    const float* prim  = (const float*)d_in[1];
    // defensive: identify by element count (image = B*C*W*W, prim = B*2*W*W)
    if (in_sizes[0] == B * 2 * W * W) {
        prim  = (const float*)d_in[0];
        image = (const float*)d_in[1];
    }

    k_initw<<<1, 1>>>();

    dim3 gb(W / TX, W / TY, B * 2);
    k_blur<<<gb, 256>>>(prim);

    k_rowscan<<<B * W, W>>>();

    k_colscan<<<(B * W + 255) / 256, 256>>>();

    k_sample<<<(B * W * W + 255) / 256, 256>>>(image, (float*)d_out);
}

// round 3
// speedup vs baseline: 1.7536x; 1.7536x over previous
#include <cuda_runtime.h>
#include <math.h>

#define W   512
#define B   32
#define C   3
#define LIM 0.03125f                     // PIX_W * EPS = (2/512)*8
#define DEF_OFF_F (1.0f + 2.0f/511.0f)   // (2 + 4/511)/2

// ---------------- scratch (static device arrays; no runtime allocs) --------
__device__ float d_gw[5];                         // 1D gaussian weights
__device__ float d_blur[(size_t)B * W * W];       // blurred prim grid, ch1 only (32MB)
__device__ float d_px[(size_t)B * W * W];         // sample x coord in pixels
__device__ float d_py[(size_t)B * W * W];         // sample y coord in pixels

// ---------------- init gaussian weights (double, matches numpy) ------------
__global__ void k_initw() {
    double sigma = 5.0 * 0.15 + 0.35;             // 1.1
    double p[5], s = 0.0;
    #pragma unroll
    for (int i = 0; i < 5; i++) {
        double d = (double)(i - 2) / sigma;
        p[i] = exp(-0.5 * d * d);
        s += p[i];
    }
    #pragma unroll
    for (int i = 0; i < 5; i++) d_gw[i] = (float)(p[i] / s);
}

__device__ __forceinline__ int refl(int i) {
    return i < 0 ? -i : (i >= W ? 2 * W - 2 - i : i);
}

// ---------------- separable 5x5 blur (ch1 only), reflect padding -----------
#define TX 64
#define TY 16
__global__ void k_blur(const float* __restrict__ pg) {
    __shared__ float sin_[TY + 4][TX + 4];
    __shared__ float svb[TY][TX + 4];
    int b = blockIdx.z;
    int bx = blockIdx.x * TX, by = blockIdx.y * TY;
    const float* src = pg + (size_t)(b * 2 + 1) * W * W;   // channel 1
    float w0 = d_gw[0], w1 = d_gw[1], w2 = d_gw[2];
    int tid = threadIdx.x;                                 // 256 threads

    for (int i = tid; i < (TY + 4) * (TX + 4); i += 256) {
        int r = i / (TX + 4), c = i % (TX + 4);
        sin_[r][c] = src[(size_t)refl(by + r - 2) * W + refl(bx + c - 2)];
    }
    __syncthreads();
    for (int i = tid; i < TY * (TX + 4); i += 256) {
        int r = i / (TX + 4), c = i % (TX + 4);
        svb[r][c] = w0 * (sin_[r][c] + sin_[r + 4][c])
                  + w1 * (sin_[r + 1][c] + sin_[r + 3][c])
                  + w2 * sin_[r + 2][c];
    }
    __syncthreads();
    float* dst = d_blur + (size_t)b * W * W;
    for (int i = tid; i < TY * TX; i += 256) {
        int r = i / TX, c = i % TX;
        float v = w0 * (svb[r][c] + svb[r][c + 4])
                + w1 * (svb[r][c + 1] + svb[r][c + 3])
                + w2 * svb[r][c + 2];
        dst[(size_t)(by + r) * W + (bx + c)] = v;
    }
}

// ---- x-channel: fused blur(ch0) + diff -> relu -> inclusive row scan ------
__global__ void k_rowscan(const float* __restrict__ pg) {
    int row = blockIdx.x;                 // b*W + y
    int b = row >> 9, y = row & 511;
    int x = threadIdx.x;                  // 512 threads
    const float* src = pg + (size_t)(b * 2) * W * W;   // channel 0

    __shared__ float srows[5][W];
    __shared__ float vb[W];
    __shared__ float ss[W];
    __shared__ float wsum[16];

    // load 5 source rows (vertical reflect)
    #pragma unroll
    for (int r = 0; r < 5; r++)
        srows[r][x] = src[(size_t)refl(y + r - 2) * W + x];
    __syncthreads();

    float w0 = d_gw[0], w1 = d_gw[1], w2 = d_gw[2];
    vb[x] = w0 * (srows[0][x] + srows[4][x])
          + w1 * (srows[1][x] + srows[3][x])
          + w2 * srows[2][x];
    __syncthreads();
    float bl = w0 * (vb[refl(x - 2)] + vb[refl(x + 2)])
             + w1 * (vb[refl(x - 1)] + vb[refl(x + 1)])
             + w2 * vb[x];

    float iden = (2.0f * x - (float)(W - 1)) * (1.0f / (W - 1));
    float sv = bl + iden + DEF_OFF_F;
    ss[x] = sv;
    __syncthreads();
    float a = (x == 0) ? fmaxf(sv, 0.f) : fmaxf(sv - ss[x - 1], 0.f);

    int lane = x & 31, warp = x >> 5;
    float v = a;
    #pragma unroll
    for (int o = 1; o < 32; o <<= 1) {
        float n = __shfl_up_sync(0xffffffffu, v, o);
        if (lane >= o) v += n;
    }
    if (lane == 31) wsum[warp] = v;
    __syncthreads();
    if (warp == 0) {
        float wv = (lane < 16) ? wsum[lane] : 0.f;
        #pragma unroll
        for (int o = 1; o < 16; o <<= 1) {
            float n = __shfl_up_sync(0xffffffffu, wv, o);
            if (lane >= o) wv += n;
        }
        if (lane < 16) wsum[lane] = wv;
    }
    __syncthreads();
    float sx2 = v + (warp ? wsum[warp - 1] : 0.f);

    float pgv = sx2 - DEF_OFF_F - iden;
    pgv = fminf(fmaxf(pgv, -LIM), LIM);
    float gx = fminf(fmaxf(pgv + iden, -1.f), 1.f);
    d_px[(size_t)row * W + x] = (gx + 1.f) * 0.5f * (float)(W - 1);
}

// ---- y-channel: tiled parallel column scan (32 cols x 512 rows / block) ---
#define SEG 32            // rows per thread
#define NSEG (W / SEG)    // 16 segments per column
__global__ void k_colscan() {
    __shared__ float segsum[NSEG][33];     // [ty][tx], padded
    int tx = threadIdx.x;                  // 0..31 (column within tile)
    int ty = threadIdx.y;                  // 0..15 (segment index)
    int x = blockIdx.x * 32 + tx;
    int b = blockIdx.y;
    const float* g = d_blur + (size_t)b * W * W + x;
    float* py = d_py + (size_t)b * W * W + x;

    int y0 = ty * SEG;
    float vals[SEG];

    // previous row's s (for the diff); segment 0 starts from zero-pad rule
    float prev = 0.f;
    if (ty > 0) {
        int yp = y0 - 1;
        float idenp = (2.0f * yp - (float)(W - 1)) * (1.0f / (W - 1));
        prev = g[(size_t)yp * W] + idenp + DEF_OFF_F;
    }

    float run = 0.f;
    #pragma unroll
    for (int r = 0; r < SEG; r++) {
        int y = y0 + r;
        float iden = (2.0f * y - (float)(W - 1)) * (1.0f / (W - 1));
        float s = g[(size_t)y * W] + iden + DEF_OFF_F;
        float a = (ty == 0 && r == 0) ? fmaxf(s, 0.f) : fmaxf(s - prev, 0.f);
        prev = s;
        run += a;
        vals[r] = run;
    }
    segsum[ty][tx] = run;
    __syncthreads();

    // exclusive prefix over segments (serial 16-step, done by warp 0)
    if (ty == 0) {
        float off = 0.f;
        #pragma unroll
        for (int k = 0; k < NSEG; k++) {
            float t = segsum[k][tx];
            segsum[k][tx] = off;
            off += t;
        }
    }
    __syncthreads();
    float offset = segsum[ty][tx];

    #pragma unroll
    for (int r = 0; r < SEG; r++) {
        int y = y0 + r;
        float iden = (2.0f * y - (float)(W - 1)) * (1.0f / (W - 1));
        float sy2 = vals[r] + offset;
        float pgv = sy2 - DEF_OFF_F - iden;
        pgv = fminf(fmaxf(pgv, -LIM), LIM);
        float gy = fminf(fmaxf(pgv + iden, -1.f), 1.f);
        py[(size_t)y * W] = (gy + 1.f) * 0.5f * (float)(W - 1);
    }
}

// ---------------- bilinear grid sample --------------------------------------
__global__ void k_sample(const float* __restrict__ img, float* __restrict__ out) {
    int idx = blockIdx.x * blockDim.x + threadIdx.x;   // b*W*W + y*W + x
    if (idx >= B * W * W) return;
    int x = idx & 511, y = (idx >> 9) & 511, b = idx >> 18;

    float fx = d_px[idx], fy = d_py[idx];
    float x0f = floorf(fx), y0f = floorf(fy);
    int x0 = (int)x0f, y0 = (int)y0f;
    int x1 = x0 + 1, y1 = y0 + 1;
    float wx1 = fx - x0f, wx0 = 1.f - wx1;
    float wy1 = fy - y0f, wy0 = 1.f - wy1;

    bool vx0 = (x0 >= 0) & (x0 < W);
    bool vx1 = (x1 >= 0) & (x1 < W);
    bool vy0 = (y0 >= 0) & (y0 < W);
    bool vy1 = (y1 >= 0) & (y1 < W);

    int x0c = min(max(x0, 0), W - 1), x1c = min(max(x1, 0), W - 1);
    int y0c = min(max(y0, 0), W - 1), y1c = min(max(y1, 0), W - 1);

    float w00 = wx0 * wy0 * (float)(vx0 && vy0);
    float w10 = wx1 * wy0 * (float)(vx1 && vy0);
    float w01 = wx0 * wy1 * (float)(vx0 && vy1);
    float w11 = wx1 * wy1 * (float)(vx1 && vy1);

    const float* ib = img + (size_t)b * C * W * W;
    size_t o00 = (size_t)y0c * W + x0c, o10 = (size_t)y0c * W + x1c;
    size_t o01 = (size_t)y1c * W + x0c, o11 = (size_t)y1c * W + x1c;
    #pragma unroll
    for (int c = 0; c < C; c++) {
        const float* ic = ib + (size_t)c * W * W;
        float v = w00 * __ldg(ic + o00) + w10 * __ldg(ic + o10)
                + w01 * __ldg(ic + o01) + w11 * __ldg(ic + o11);
        out[((size_t)(b * C + c) * W + y) * W + x] = v;
    }
}

// ---------------- launch -----------------------------------------------------
extern "C" void kernel_launch(void* const* d_in, const int* in_sizes, int n_in,
                              void* d_out, int out_size) {
    const float* image = (const float*)d_in[0];
    const float* prim  = (const float*)d_in[1];
    if (in_sizes[0] == B * 2 * W * W) {     // defensive input identification
        prim  = (const float*)d_in[0];
        image = (const float*)d_in[1];
    }

    k_initw<<<1, 1>>>();

    dim3 gb(W / TX, W / TY, B);
    k_blur<<<gb, 256>>>(prim);

    k_rowscan<<<B * W, W>>>(prim);

    dim3 cb(32, NSEG);
    dim3 cg(W / 32, B);
    k_colscan<<<cg, cb>>>();

    k_sample<<<(B * W * W + 255) / 256, 256>>>(image, (float*)d_out);
}

// round 4
// speedup vs baseline: 3.1831x; 1.8151x over previous
#include <cuda_runtime.h>
#include <math.h>

#define W   512
#define B   32
#define C   3
#define LIM 0.03125f                     // PIX_W * EPS = (2/512)*8
#define DEF_OFF_F (1.0f + 2.0f/511.0f)   // (2 + 4/511)/2
#define FULL 0xffffffffu

// ---------------- scratch (static device arrays; no runtime allocs) --------
__device__ float d_gw[5];                         // 1D gaussian weights
__device__ float d_px[(size_t)B * W * W];         // sample x coord in pixels
__device__ float d_py[(size_t)B * W * W];         // sample y coord in pixels

// ---------------- init gaussian weights (double, matches numpy) ------------
__global__ void k_initw() {
    double sigma = 5.0 * 0.15 + 0.35;             // 1.1
    double p[5], s = 0.0;
    #pragma unroll
    for (int i = 0; i < 5; i++) {
        double d = (double)(i - 2) / sigma;
        p[i] = exp(-0.5 * d * d);
        s += p[i];
    }
    #pragma unroll
    for (int i = 0; i < 5; i++) d_gw[i] = (float)(p[i] / s);
}

__device__ __forceinline__ int refl(int i) {
    return i < 0 ? -i : (i >= W ? 2 * W - 2 - i : i);
}

// ==== x-channel: fused blur(ch0) + diff->relu->row scan, 8 rows/block =======
#define RROWS 8
__global__ void k_rowscan(const float* __restrict__ pg) {
    __shared__ float ssrc[RROWS + 4][W];   // 24KB
    __shared__ float svb[RROWS][W];        // 16KB
    int b = blockIdx.y;
    int y0 = blockIdx.x * RROWS;
    int tid = threadIdx.x;                 // 256 threads = 8 warps
    const float* src = pg + (size_t)(b * 2) * W * W;   // channel 0

    // load RROWS+4 source rows (vertical reflect)
    for (int i = tid; i < (RROWS + 4) * W; i += 256) {
        int r = i >> 9, x = i & 511;
        ssrc[r][x] = src[(size_t)refl(y0 + r - 2) * W + x];
    }
    __syncthreads();

    float w0 = d_gw[0], w1 = d_gw[1], w2 = d_gw[2];
    int warp = tid >> 5, lane = tid & 31;
    int y = y0 + warp;

    // vertical blur for this warp's row
    #pragma unroll
    for (int k = 0; k < 16; k++) {
        int x = k * 32 + lane;
        svb[warp][x] = w0 * (ssrc[warp][x] + ssrc[warp + 4][x])
                     + w1 * (ssrc[warp + 1][x] + ssrc[warp + 3][x])
                     + w2 * ssrc[warp + 2][x];
    }
    __syncwarp();

    // horizontal blur + diff -> relu -> inclusive scan (chunked warp scan)
    float last31 = 0.f;   // s at previous chunk's x (for lane 0 diff); 0 => pad rule
    float run = 0.f;
    float* pxo = d_px + ((size_t)b * W + y) * W;
    #pragma unroll
    for (int k = 0; k < 16; k++) {
        int x = k * 32 + lane;
        float bl = w0 * (svb[warp][refl(x - 2)] + svb[warp][refl(x + 2)])
                 + w1 * (svb[warp][refl(x - 1)] + svb[warp][refl(x + 1)])
                 + w2 * svb[warp][x];
        float iden = (2.0f * x - (float)(W - 1)) * (1.0f / (W - 1));
        float s = bl + iden + DEF_OFF_F;
        float sprev = __shfl_up_sync(FULL, s, 1);
        if (lane == 0) sprev = last31;
        float a = fmaxf(s - sprev, 0.f);
        last31 = __shfl_sync(FULL, s, 31);

        float v = a;
        #pragma unroll
        for (int o = 1; o < 32; o <<= 1) {
            float n = __shfl_up_sync(FULL, v, o);
            if (lane >= o) v += n;
        }
        float sx2 = run + v;
        run += __shfl_sync(FULL, v, 31);

        float pgv = sx2 - DEF_OFF_F - iden;
        pgv = fminf(fmaxf(pgv, -LIM), LIM);
        float gx = fminf(fmaxf(pgv + iden, -1.f), 1.f);
        pxo[x] = (gx + 1.f) * 0.5f * (float)(W - 1);
    }
}

// ==== y-channel: fused blur(ch1) + tiled column scan =========================
// block (32,16): 32 columns x full 512 rows; hblur tile in dynamic smem,
// vertical blur via rolling register window during the serial scan.
#define SEG 32
#define NSEG (W / SEG)
__global__ void k_colscan(const float* __restrict__ pg) {
    extern __shared__ float hb[];          // [W][32] = 64KB
    __shared__ float segsum[NSEG][33];
    int tx = threadIdx.x;                  // 0..31 column in tile
    int ty = threadIdx.y;                  // 0..15 segment
    int x = blockIdx.x * 32 + tx;
    int b = blockIdx.y;
    const float* src = pg + (size_t)(b * 2 + 1) * W * W;   // channel 1
    float w0 = d_gw[0], w1 = d_gw[1], w2 = d_gw[2];

    int xm2 = refl(x - 2), xm1 = refl(x - 1), xp1 = refl(x + 1), xp2 = refl(x + 2);

    // phase 1: horizontal blur for this column, rows ty*32 .. ty*32+31
    int y0 = ty * SEG;
    #pragma unroll 4
    for (int r = 0; r < SEG; r++) {
        const float* row = src + (size_t)(y0 + r) * W;
        hb[(y0 + r) * 32 + tx] =
            w0 * (__ldg(row + xm2) + __ldg(row + xp2))
          + w1 * (__ldg(row + xm1) + __ldg(row + xp1))
          + w2 * __ldg(row + x);
    }
    __syncthreads();

    // phase 2: serial scan with rolling vertical-blur window
    float h0 = hb[refl(y0 - 2) * 32 + tx];
    float h1 = hb[refl(y0 - 1) * 32 + tx];
    float h2 = hb[y0 * 32 + tx];
    float h3 = hb[(y0 + 1) * 32 + tx];
    float h4 = hb[refl(y0 + 2) * 32 + tx];

    float prev = 0.f;
    if (ty > 0) {   // s at row y0-1 (needs vblur of y0-1)
        float g0 = hb[refl(y0 - 3) * 32 + tx];
        float vbp = w0 * (g0 + h3) + w1 * (h0 + h2) + w2 * h1;
        float idenp = (2.0f * (y0 - 1) - (float)(W - 1)) * (1.0f / (W - 1));
        prev = vbp + idenp + DEF_OFF_F;
    }

    float vals[SEG];
    float run = 0.f;
    #pragma unroll
    for (int r = 0; r < SEG; r++) {
        int y = y0 + r;
        float vb = w0 * (h0 + h4) + w1 * (h1 + h3) + w2 * h2;
        float iden = (2.0f * y - (float)(W - 1)) * (1.0f / (W - 1));
        float s = vb + iden + DEF_OFF_F;
        float a = fmaxf(s - prev, 0.f);        // prev==0 for (ty==0,r==0) = pad rule
        prev = s;
        run += a;
        vals[r] = run;
        h0 = h1; h1 = h2; h2 = h3; h3 = h4;
        h4 = hb[refl(y + 3) * 32 + tx];
    }
    segsum[ty][tx] = run;
    __syncthreads();

    if (ty == 0) {   // exclusive prefix over segments
        float off = 0.f;
        #pragma unroll
        for (int k = 0; k < NSEG; k++) {
            float t = segsum[k][tx];
            segsum[k][tx] = off;
            off += t;
        }
    }
    __syncthreads();
    float offset = segsum[ty][tx];

    float* py = d_py + (size_t)b * W * W + x;
    #pragma unroll
    for (int r = 0; r < SEG; r++) {
        int y = y0 + r;
        float iden = (2.0f * y - (float)(W - 1)) * (1.0f / (W - 1));
        float sy2 = vals[r] + offset;
        float pgv = sy2 - DEF_OFF_F - iden;
        pgv = fminf(fmaxf(pgv, -LIM), LIM);
        float gy = fminf(fmaxf(pgv + iden, -1.f), 1.f);
        py[(size_t)y * W] = (gy + 1.f) * 0.5f * (float)(W - 1);
    }
}

// ==== bilinear grid sample, 2 pixels / thread ================================
__device__ __forceinline__ void samp1(const float* __restrict__ ib,
                                      float fx, float fy,
                                      float& r0, float& r1, float& r2) {
    float x0f = floorf(fx), y0f = floorf(fy);
    int x0 = (int)x0f, y0 = (int)y0f;
    int x1 = x0 + 1, y1 = y0 + 1;
    float wx1 = fx - x0f, wx0 = 1.f - wx1;
    float wy1 = fy - y0f, wy0 = 1.f - wy1;

    bool vx0 = (x0 >= 0) & (x0 < W);
    bool vx1 = (x1 >= 0) & (x1 < W);
    bool vy0 = (y0 >= 0) & (y0 < W);
    bool vy1 = (y1 >= 0) & (y1 < W);

    int x0c = min(max(x0, 0), W - 1), x1c = min(max(x1, 0), W - 1);
    int y0c = min(max(y0, 0), W - 1), y1c = min(max(y1, 0), W - 1);

    float w00 = wx0 * wy0 * (float)(vx0 && vy0);
    float w10 = wx1 * wy0 * (float)(vx1 && vy0);
    float w01 = wx0 * wy1 * (float)(vx0 && vy1);
    float w11 = wx1 * wy1 * (float)(vx1 && vy1);

    size_t o00 = (size_t)y0c * W + x0c, o10 = (size_t)y0c * W + x1c;
    size_t o01 = (size_t)y1c * W + x0c, o11 = (size_t)y1c * W + x1c;
    r0 = w00 * __ldg(ib + o00) + w10 * __ldg(ib + o10)
       + w01 * __ldg(ib + o01) + w11 * __ldg(ib + o11);
    const float* i1 = ib + (size_t)W * W;
    r1 = w00 * __ldg(i1 + o00) + w10 * __ldg(i1 + o10)
       + w01 * __ldg(i1 + o01) + w11 * __ldg(i1 + o11);
    const float* i2 = ib + (size_t)2 * W * W;
    r2 = w00 * __ldg(i2 + o00) + w10 * __ldg(i2 + o10)
       + w01 * __ldg(i2 + o01) + w11 * __ldg(i2 + o11);
}

__global__ void k_sample(const float* __restrict__ img, float* __restrict__ out) {
    int t = blockIdx.x * blockDim.x + threadIdx.x;     // pair index
    if (t >= B * W * W / 2) return;
    int y = (t >> 8) & 511, b = t >> 17;

    float2 fx2 = ((const float2*)d_px)[t];
    float2 fy2 = ((const float2*)d_py)[t];

    const float* ib = img + (size_t)b * C * W * W;
    float a0, a1, a2, b0, b1, b2;
    samp1(ib, fx2.x, fy2.x, a0, a1, a2);
    samp1(ib, fx2.y, fy2.y, b0, b1, b2);

    size_t orow = ((size_t)(b * C) * W + y) * W;
    int xo = (t & 255) * 2;
    ((float2*)(out + orow + xo))[0]                       = make_float2(a0, b0);
    ((float2*)(out + orow + (size_t)W * W + xo))[0]       = make_float2(a1, b1);
    ((float2*)(out + orow + (size_t)2 * W * W + xo))[0]   = make_float2(a2, b2);
}

// ---------------- launch -----------------------------------------------------
extern "C" void kernel_launch(void* const* d_in, const int* in_sizes, int n_in,
                              void* d_out, int out_size) {
    const float* image = (const float*)d_in[0];
    const float* prim  = (const float*)d_in[1];
    if (in_sizes[0] == B * 2 * W * W) {     // defensive input identification
        prim  = (const float*)d_in[0];
        image = (const float*)d_in[1];
    }

    static bool attr_done = false;
    if (!attr_done) {
        cudaFuncSetAttribute(k_colscan,
                             cudaFuncAttributeMaxDynamicSharedMemorySize,
                             W * 32 * (int)sizeof(float));
        attr_done = true;
    }

    k_initw<<<1, 1>>>();

    dim3 rg(W / RROWS, B);
    k_rowscan<<<rg, 256>>>(prim);

    dim3 cb(32, NSEG);
    dim3 cg(W / 32, B);
    k_colscan<<<cg, cb, W * 32 * sizeof(float)>>>(prim);

    k_sample<<<(B * W * W / 2 + 255) / 256, 256>>>(image, (float*)d_out);
}